// round 13
// baseline (speedup 1.0000x reference)
#include <cuda_runtime.h>
#include <cuda_fp16.h>
#include <math.h>
#include <stdint.h>

// ---------------- problem constants ----------------
#define Bc     8
#define Tc     2048
#define VDIMc  1024
#define ADIMc  768
#define DMc    256
#define HIDc   1024
#define MROWS  (Bc * Tc)          // 16384
#define XDIM   (3 * DMc)          // 768

// ---------------- scratch (device globals; no allocation allowed) ----------------
__device__ float g_v   [MROWS * DMc];
__device__ float g_a   [MROWS * DMc];
__device__ float g_actx[MROWS * DMc];
__device__ float g_part[MROWS * 8];
__device__ int   g_cnt [MROWS / 128];               // per row-block arrival counter

__device__ __half g_Vh[(size_t)MROWS * VDIMc];      // fp16 activations
__device__ __half g_Ah[(size_t)MROWS * ADIMc];
__device__ __half g_Xh[(size_t)MROWS * XDIM];
__device__ __half g_Bv[DMc  * VDIMc];               // fp16 transposed weights [N,K]
__device__ __half g_Ba[DMc  * ADIMc];
__device__ __half g_B1[HIDc * XDIM];

// ---------------- helpers ----------------
__device__ __forceinline__ uint32_t smem_u32(const void* p) {
    uint32_t a;
    asm("{ .reg .u64 t; cvta.to.shared.u64 t, %1; cvt.u32.u64 %0, t; }" : "=r"(a) : "l"(p));
    return a;
}
__device__ __forceinline__ float gelu_exact(float h) {
    return 0.5f * h * (1.f + erff(h * 0.70710678118654752f));
}

#define LDSM4(rg, addr) \
    asm volatile("ldmatrix.sync.aligned.m8n8.x4.shared.b16 {%0,%1,%2,%3}, [%4];" \
        : "=r"((rg)[0]), "=r"((rg)[1]), "=r"((rg)[2]), "=r"((rg)[3]) : "r"(addr))

#define MMA16816(d, a, b) \
    asm volatile("mma.sync.aligned.m16n8k16.row.col.f32.f16.f16.f32 " \
        "{%0,%1,%2,%3}, {%4,%5,%6,%7}, {%8,%9}, {%0,%1,%2,%3};" \
        : "+f"((d)[0]), "+f"((d)[1]), "+f"((d)[2]), "+f"((d)[3]) \
        : "r"((a)[0]), "r"((a)[1]), "r"((a)[2]), "r"((a)[3]), "r"((b)[0]), "r"((b)[1]))

#define CP_ASYNC16(dst, src) \
    asm volatile("cp.async.cg.shared.global [%0], [%1], 16;" :: "r"(dst), "l"(src) : "memory")
#define CP_COMMIT() asm volatile("cp.async.commit_group;" ::: "memory")
#define CP_WAIT1()  asm volatile("cp.async.wait_group 1;" ::: "memory")

// sub-tile: 128 rows x 64 bytes (32 fp16), XOR swizzle on 16B groups
__device__ __forceinline__ uint32_t sw_off(int r, int c16) {
    return (uint32_t)(((r << 6) + (c16 << 4)) ^ ((r & 3) << 4));
}

// ---------------- plain fp16 GEMM body: C[128,128] tile = A @ B^T (+bias) ----------------
// stage = 2 k-chunks {A0,B0,A1,B1}, 8KB sub-tiles -> 32KB/stage
#define STAGES 3
#define STAGEB 32768
static constexpr int SM_EPI    = STAGES * STAGEB;    // 98304
static constexpr int GSM_TOTAL = SM_EPI + 1536;      // 99840

template <bool FUSE>
__device__ __forceinline__ void gemm_body(
    char* smem, const __half* __restrict__ A, const __half* __restrict__ Bm,
    const float* __restrict__ bias, const float* __restrict__ W2,
    float* __restrict__ out, int K, int Ntot, int bx, int by, int nxt)
{
    const uint32_t sbase = smem_u32(smem);
    const int tid  = threadIdx.x;
    const int lane = tid & 31, warp = tid >> 5;
    const int wm = warp >> 2, wn = warp & 3;          // 2 x 4 warp grid (64m x 32n)

    float* sBias = (float*)(smem + SM_EPI);
    float* sW2   = (float*)(smem + SM_EPI + 512);
    float* sRow  = (float*)(smem + SM_EPI + 1024);
    if (tid < 128) {
        sBias[tid] = bias[bx * 128 + tid];
        if (FUSE) { sW2[tid] = W2[bx * 128 + tid]; sRow[tid] = 0.f; }
    }

    const int ni = K >> 6;            // dual-chunk iterations (64 K each)
    const int cr = tid >> 2, cc = tid & 3;

    const __half* Ab = A  + (size_t)(by * 128 + cr) * K + cc * 8;
    const __half* Bb = Bm + (size_t)(bx * 128 + cr) * K + cc * 8;

    float acc[4][4][4];
#pragma unroll
    for (int i = 0; i < 4; i++)
#pragma unroll
        for (int j = 0; j < 4; j++)
#pragma unroll
            for (int q = 0; q < 4; q++) acc[i][j][q] = 0.f;

    auto load_stage = [&](int stage, int it) {
        const uint32_t s0 = sbase + stage * STAGEB;
#pragma unroll
        for (int h = 0; h < 2; h++) {
            const int kofs = (2 * it + h) * 32;
            const __half* a0 = Ab + kofs;
            const __half* b0 = Bb + kofs;
            const uint32_t sA = s0 + h * 16384;
            const uint32_t sB = sA + 8192;
            CP_ASYNC16(sA + sw_off(cr,      cc), a0);
            CP_ASYNC16(sA + sw_off(cr + 64, cc), a0 + (size_t)64 * K);
            CP_ASYNC16(sB + sw_off(cr,      cc), b0);
            CP_ASYNC16(sB + sw_off(cr + 64, cc), b0 + (size_t)64 * K);
        }
    };

    load_stage(0, 0); CP_COMMIT();
    load_stage(1, 1); CP_COMMIT();

    const int arow  = wm * 64 + (lane & 15);
    const int acsel = lane >> 4;
    const int brow  = wn * 32 + (lane & 7) + ((lane >> 4) << 3);
    const int bcsel = (lane >> 3) & 1;

    for (int it = 0; it < ni; it++) {
        CP_WAIT1();
        __syncthreads();

        const int nx = it + 2;
        if (nx < ni) load_stage(nx % STAGES, nx);
        CP_COMMIT();

#pragma unroll
        for (int h = 0; h < 2; h++) {
            const uint32_t sA = sbase + (it % STAGES) * STAGEB + h * 16384;
            const uint32_t sB = sA + 8192;
#pragma unroll
            for (int ks = 0; ks < 2; ks++) {
                uint32_t afr[4][4], bfr[2][4];
#pragma unroll
                for (int mt = 0; mt < 4; mt++)
                    LDSM4(afr[mt], sA + sw_off(arow + mt * 16, ks * 2 + acsel));
#pragma unroll
                for (int nb = 0; nb < 2; nb++)
                    LDSM4(bfr[nb], sB + sw_off(brow + nb * 16, ks * 2 + bcsel));
#pragma unroll
                for (int mt = 0; mt < 4; mt++) {
#pragma unroll
                    for (int n8 = 0; n8 < 4; n8++) {
                        uint32_t bb[2] = { bfr[n8 >> 1][(n8 & 1) * 2], bfr[n8 >> 1][(n8 & 1) * 2 + 1] };
                        MMA16816(acc[mt][n8], afr[mt], bb);
                    }
                }
            }
        }
        // no trailing sync: next iteration's leading sync protects the stage
    }

    // ---- epilogue ----
    if (!FUSE) {
#pragma unroll
        for (int mt = 0; mt < 4; mt++) {
            const int row = by * 128 + wm * 64 + mt * 16 + (lane >> 2);
#pragma unroll
            for (int n8 = 0; n8 < 4; n8++) {
                const int lc  = wn * 32 + n8 * 8 + (lane & 3) * 2;
                const int col = bx * 128 + lc;
                float2 v0 = { acc[mt][n8][0] + sBias[lc], acc[mt][n8][1] + sBias[lc + 1] };
                float2 v1 = { acc[mt][n8][2] + sBias[lc], acc[mt][n8][3] + sBias[lc + 1] };
                *reinterpret_cast<float2*>(out + (size_t)row * Ntot + col)       = v0;
                *reinterpret_cast<float2*>(out + (size_t)(row + 8) * Ntot + col) = v1;
            }
        }
    } else {
#pragma unroll
        for (int mt = 0; mt < 4; mt++) {
            float pA = 0.f, pB = 0.f;
#pragma unroll
            for (int n8 = 0; n8 < 4; n8++) {
                const int lc = wn * 32 + n8 * 8 + (lane & 3) * 2;
                pA += gelu_exact(acc[mt][n8][0] + sBias[lc])     * sW2[lc];
                pA += gelu_exact(acc[mt][n8][1] + sBias[lc + 1]) * sW2[lc + 1];
                pB += gelu_exact(acc[mt][n8][2] + sBias[lc])     * sW2[lc];
                pB += gelu_exact(acc[mt][n8][3] + sBias[lc + 1]) * sW2[lc + 1];
            }
            pA += __shfl_xor_sync(0xffffffffu, pA, 1);
            pA += __shfl_xor_sync(0xffffffffu, pA, 2);
            pB += __shfl_xor_sync(0xffffffffu, pB, 1);
            pB += __shfl_xor_sync(0xffffffffu, pB, 2);
            if ((lane & 3) == 0) {
                atomicAdd(&sRow[wm * 64 + mt * 16 + (lane >> 2)],     pA);
                atomicAdd(&sRow[wm * 64 + mt * 16 + (lane >> 2) + 8], pB);
            }
        }
        __syncthreads();
        if (tid < 128)
            out[(size_t)(by * 128 + tid) * nxt + bx] = sRow[tid];
    }
}

// merged projection GEMM: z=0 -> video (K=VDIMc), z=1 -> audio (K=ADIMc)
__global__ void __launch_bounds__(256, 2)
proj_gemm(const __half* __restrict__ Av, const __half* __restrict__ Bv,
          const float* __restrict__ bv, float* __restrict__ ov,
          const __half* __restrict__ Aa, const __half* __restrict__ Ba,
          const float* __restrict__ ba, float* __restrict__ oa)
{
    extern __shared__ char smem[];
    if (blockIdx.z == 0)
        gemm_body<false>(smem, Av, Bv, bv, nullptr, ov, VDIMc, DMc,
                         blockIdx.x, blockIdx.y, 0);
    else
        gemm_body<false>(smem, Aa, Ba, ba, nullptr, oa, ADIMc, DMc,
                         blockIdx.x, blockIdx.y, 0);
}

// gate MLP GEMM with fused gelu + W2 partial reduction + last-CTA final blend
__global__ void __launch_bounds__(256, 2)
mlp_gemm(const __half* __restrict__ A, const __half* __restrict__ Bm,
         const float* __restrict__ bias, const float* __restrict__ W2,
         float* __restrict__ part, const float* __restrict__ b2,
         float* __restrict__ out)
{
    extern __shared__ char smem[];
    gemm_body<true>(smem, A, Bm, bias, W2, part, XDIM, HIDc,
                    blockIdx.x, blockIdx.y, gridDim.x);

    // ---- last-CTA-per-row-block performs the gate + blend ----
    __threadfence();
    __syncthreads();
    __shared__ int sLast;
    if (threadIdx.x == 0)
        sLast = (atomicAdd(&g_cnt[blockIdx.y], 1) == (int)gridDim.x - 1) ? 1 : 0;
    __syncthreads();
    if (sLast) {
        __threadfence();
        const int lane = threadIdx.x & 31, w = threadIdx.x >> 5;
        const float l0 = b2[0];
        for (int rr = 0; rr < 16; rr++) {
            const size_t row = (size_t)blockIdx.y * 128 + w * 16 + rr;
            float l = l0;
#pragma unroll
            for (int p = 0; p < 8; p++) l += g_part[row * 8 + p];
            l = fminf(fmaxf(l, -12.f), 12.f);
            float g = 1.f / (1.f + expf(-l));
            g = fminf(fmaxf(g, 0.05f), 0.95f);
            const float4* pa = reinterpret_cast<const float4*>(g_actx + row * DMc);
            const float4* pv = reinterpret_cast<const float4*>(g_v    + row * DMc);
            float4* po = reinterpret_cast<float4*>(out + row * DMc);
#pragma unroll
            for (int h = 0; h < 2; h++) {
                float4 a4 = pa[lane + h * 32], v4 = pv[lane + h * 32], o4;
                o4.x = g * a4.x + (1.f - g) * v4.x;
                o4.y = g * a4.y + (1.f - g) * v4.y;
                o4.z = g * a4.z + (1.f - g) * v4.z;
                o4.w = g * a4.w + (1.f - g) * v4.w;
                po[lane + h * 32] = o4;
            }
        }
    }
}

// ---------------- mega prep: activation converts + weight transposes, one launch ----------
#define NB_V (MROWS * VDIMc / 4 / 256)    // 16384
#define NB_A (MROWS * ADIMc / 4 / 256)    // 12288
#define NB_WV ((VDIMc / 32) * (DMc / 32))   // 256
#define NB_WA ((ADIMc / 32) * (DMc / 32))   // 192
#define NB_W1 ((XDIM / 32) * (HIDc / 32))   // 768
#define NB_TOTAL (NB_V + NB_A + NB_WV + NB_WA + NB_W1)

__device__ __forceinline__ void cvt_body(const float4* __restrict__ X,
                                         __half* __restrict__ dst, int i)
{
    float4 x = X[i];
    ushort4 v;
    v.x = __half_as_ushort(__float2half(x.x));
    v.y = __half_as_ushort(__float2half(x.y));
    v.z = __half_as_ushort(__float2half(x.z));
    v.w = __half_as_ushort(__float2half(x.w));
    *reinterpret_cast<ushort4*>(dst + 4 * (size_t)i) = v;
}

__device__ __forceinline__ void wcvtT_body(float (*tile)[33],
                                           const float* __restrict__ W,
                                           __half* __restrict__ dst,
                                           int K, int N, int bxk, int byn)
{
    const int k0 = bxk * 32, n0 = byn * 32;
    const int tx = threadIdx.x & 31, ty8 = threadIdx.x >> 5;
#pragma unroll
    for (int i = 0; i < 4; i++) {
        int ty = ty8 + i * 8;
        tile[ty][tx] = W[(size_t)(k0 + ty) * N + n0 + tx];
    }
    __syncthreads();
#pragma unroll
    for (int i = 0; i < 4; i++) {
        int ny = ty8 + i * 8;
        dst[(size_t)(n0 + ny) * K + k0 + tx] = __float2half(tile[tx][ny]);
    }
}

__global__ __launch_bounds__(256)
void prep_kernel(const float4* __restrict__ video, const float4* __restrict__ audio,
                 const float* __restrict__ Wv, const float* __restrict__ Wa,
                 const float* __restrict__ W1,
                 __half* __restrict__ vh, __half* __restrict__ ah,
                 __half* __restrict__ bvw, __half* __restrict__ baw,
                 __half* __restrict__ b1w)
{
    __shared__ float tile[32][33];
    const int bid = blockIdx.x;
    if (bid == 0 && threadIdx.x < MROWS / 128)
        g_cnt[threadIdx.x] = 0;                    // reset arrival counters each replay
    if (bid < NB_V) {
        cvt_body(video, vh, bid * 256 + threadIdx.x);
    } else if (bid < NB_V + NB_A) {
        cvt_body(audio, ah, (bid - NB_V) * 256 + threadIdx.x);
    } else if (bid < NB_V + NB_A + NB_WV) {
        int j = bid - (NB_V + NB_A);
        wcvtT_body(tile, Wv, bvw, VDIMc, DMc, j % (VDIMc / 32), j / (VDIMc / 32));
    } else if (bid < NB_V + NB_A + NB_WV + NB_WA) {
        int j = bid - (NB_V + NB_A + NB_WV);
        wcvtT_body(tile, Wa, baw, ADIMc, DMc, j % (ADIMc / 32), j / (ADIMc / 32));
    } else {
        int j = bid - (NB_V + NB_A + NB_WV + NB_WA);
        wcvtT_body(tile, W1, b1w, XDIM, HIDc, j % (XDIM / 32), j / (XDIM / 32));
    }
}

// ---------------- warp-per-row LayerNorm (DM=256), 8 rows/block, both tensors ----------------
__global__ __launch_bounds__(256)
void ln8_kernel()
{
    const int lane = threadIdx.x & 31, w = threadIdx.x >> 5;
    float* X = (blockIdx.y == 0) ? g_v : g_a;
    const size_t row = (size_t)blockIdx.x * 8 + w;
    float4* p = reinterpret_cast<float4*>(X + row * DMc);
    float4 x0 = p[lane], x1 = p[lane + 32];
    float s = x0.x + x0.y + x0.z + x0.w + x1.x + x1.y + x1.z + x1.w;
#pragma unroll
    for (int o = 16; o > 0; o >>= 1) s += __shfl_xor_sync(0xffffffffu, s, o);
    float mu = s * (1.f / DMc);
    x0.x -= mu; x0.y -= mu; x0.z -= mu; x0.w -= mu;
    x1.x -= mu; x1.y -= mu; x1.z -= mu; x1.w -= mu;
    float q = x0.x*x0.x + x0.y*x0.y + x0.z*x0.z + x0.w*x0.w
            + x1.x*x1.x + x1.y*x1.y + x1.z*x1.z + x1.w*x1.w;
#pragma unroll
    for (int o = 16; o > 0; o >>= 1) q += __shfl_xor_sync(0xffffffffu, q, o);
    float r = rsqrtf(q * (1.f / DMc) + 1e-5f);
    x0.x *= r; x0.y *= r; x0.z *= r; x0.w *= r;
    x1.x *= r; x1.y *= r; x1.z *= r; x1.w *= r;
    p[lane] = x0; p[lane + 32] = x1;
}

// ---------------- sliding-window shift + context + l2norm + X build ----------------
// One warp per 16-t chunk of one batch row; lane owns 8 d's. Running window sum with a
// 6-deep register ring: S(t) = S(t-1) + a_shift(t) - a_shift(t-6). Zero block barriers.
#define TCHUNK 16
__global__ __launch_bounds__(256)
void shiftx_kernel(const float* __restrict__ theta)
{
    const int lane = threadIdx.x & 31, w = threadIdx.x >> 5;
    const int job = blockIdx.x * 8 + w;                  // 0..1023
    const int b = job >> 7;                              // 128 chunks per batch
    const int t0 = (job & 127) * TCHUNK;

    float th = fminf(fmaxf(theta[0], -12.f), 12.f);
    float delta = 2.f + 4.f / (1.f + expf(-th));
    float dl = fminf(fmaxf(delta, 0.f), (float)(Tc - 1));
    float nf = floorf(dl);
    float alpha = dl - nf;
    const int ni = (int)nf;

    const int warm = max(0, t0 - 5);
    const int warm6 = warm + 6;
    const float* abase = g_a + (size_t)b * Tc * DMc;
    const int d0 = lane * 8;

    float ring[6][8], sum[8], r0[8], r1[8];
#pragma unroll
    for (int j = 0; j < 8; j++) sum[j] = 0.f;
#pragma unroll
    for (int k = 0; k < 6; k++)
#pragma unroll
        for (int j = 0; j < 8; j++) ring[k][j] = 0.f;

    auto loadrow = [&](int r, float* dst) {
        const float4* p = reinterpret_cast<const float4*>(abase + (size_t)r * DMc + d0);
        float4 a = p[0], c = p[1];
        dst[0] = a.x; dst[1] = a.y; dst[2] = a.z; dst[3] = a.w;
        dst[4] = c.x; dst[5] = c.y; dst[6] = c.z; dst[7] = c.w;
    };

    int jrow = max(0, warm - ni);                 // i0 at warm (never top-clamped)
    loadrow(jrow, r0);
    loadrow(min(jrow + 1, Tc - 1), r1);

    for (int tau = warm; tau < t0 + TCHUNK; tau++) {
        const int i0 = max(0, tau - ni);
        if (i0 != jrow) {                         // advanced by exactly 1
#pragma unroll
            for (int j = 0; j < 8; j++) r0[j] = r1[j];
            loadrow(min(i0 + 1, Tc - 1), r1);
            jrow = i0;
        }
        float ash[8];
#pragma unroll
        for (int j = 0; j < 8; j++) {
            ash[j] = (1.f - alpha) * r0[j] + alpha * r1[j];
            sum[j] += ash[j];
        }
        if (tau >= warm6) {
#pragma unroll
            for (int j = 0; j < 8; j++) sum[j] -= ring[0][j];
        }
#pragma unroll
        for (int k = 0; k < 5; k++)
#pragma unroll
            for (int j = 0; j < 8; j++) ring[k][j] = ring[k + 1][j];
#pragma unroll
        for (int j = 0; j < 8; j++) ring[5][j] = ash[j];

        if (tau < t0) continue;                   // warm-up only

        // ---- emit row tau ----
        const size_t row = (size_t)b * Tc + tau;
        const float inv = 1.f / (float)min(tau + 1, 6);
        float actx[8];
#pragma unroll
        for (int j = 0; j < 8; j++) actx[j] = sum[j] * inv;
        {
            float4* po = reinterpret_cast<float4*>(g_actx + row * DMc + d0);
            po[0] = make_float4(actx[0], actx[1], actx[2], actx[3]);
            po[1] = make_float4(actx[4], actx[5], actx[6], actx[7]);
        }
        float vv[8];
        {
            const float4* pv = reinterpret_cast<const float4*>(g_v + row * DMc + d0);
            float4 a = pv[0], c = pv[1];
            vv[0] = a.x; vv[1] = a.y; vv[2] = a.z; vv[3] = a.w;
            vv[4] = c.x; vv[5] = c.y; vv[6] = c.z; vv[7] = c.w;
        }
        float ssv = 0.f, ssa = 0.f;
#pragma unroll
        for (int j = 0; j < 8; j++) { ssv += vv[j] * vv[j]; ssa += actx[j] * actx[j]; }
#pragma unroll
        for (int o = 16; o > 0; o >>= 1) {
            ssv += __shfl_xor_sync(0xffffffffu, ssv, o);
            ssa += __shfl_xor_sync(0xffffffffu, ssa, o);
        }
        const float rv = 1.f / fmaxf(sqrtf(ssv), 1e-8f);
        const float ra = 1.f / fmaxf(sqrtf(ssa), 1e-8f);

        __half h8[8];
        const size_t base = row * XDIM;
#pragma unroll
        for (int j = 0; j < 8; j++) h8[j] = __float2half(actx[j] * ra);
        *reinterpret_cast<uint4*>(g_Xh + base + d0) = *reinterpret_cast<uint4*>(h8);
#pragma unroll
        for (int j = 0; j < 8; j++) h8[j] = __float2half(vv[j] * rv);
        *reinterpret_cast<uint4*>(g_Xh + base + DMc + d0) = *reinterpret_cast<uint4*>(h8);
#pragma unroll
        for (int j = 0; j < 8; j++) h8[j] = __float2half((actx[j] * ra) * (vv[j] * rv));
        *reinterpret_cast<uint4*>(g_Xh + base + 2 * DMc + d0) = *reinterpret_cast<uint4*>(h8);
    }
}

// ---------------- launch ----------------
extern "C" void kernel_launch(void* const* d_in, const int* in_sizes, int n_in,
                              void* d_out, int out_size)
{
    const float* video = (const float*)d_in[0];
    const float* audio = (const float*)d_in[1];
    const float* Wv    = (const float*)d_in[2];
    const float* bv    = (const float*)d_in[3];
    const float* Wa    = (const float*)d_in[4];
    const float* ba    = (const float*)d_in[5];
    const float* theta = (const float*)d_in[6];
    const float* W1    = (const float*)d_in[7];
    const float* b1    = (const float*)d_in[8];
    const float* W2    = (const float*)d_in[9];
    const float* b2    = (const float*)d_in[10];
    float* out = (float*)d_out;

    float *gv, *ga, *gpart;
    __half *vh, *ah, *xh, *bvw, *baw, *b1w;
    cudaGetSymbolAddress((void**)&gv, g_v);
    cudaGetSymbolAddress((void**)&ga, g_a);
    cudaGetSymbolAddress((void**)&gpart, g_part);
    cudaGetSymbolAddress((void**)&vh, g_Vh);
    cudaGetSymbolAddress((void**)&ah, g_Ah);
    cudaGetSymbolAddress((void**)&xh, g_Xh);
    cudaGetSymbolAddress((void**)&bvw, g_Bv);
    cudaGetSymbolAddress((void**)&baw, g_Ba);
    cudaGetSymbolAddress((void**)&b1w, g_B1);

    cudaFuncSetAttribute(proj_gemm, cudaFuncAttributeMaxDynamicSharedMemorySize, GSM_TOTAL);
    cudaFuncSetAttribute(mlp_gemm,  cudaFuncAttributeMaxDynamicSharedMemorySize, GSM_TOTAL);

    // single prep launch: converts + transposes + counter reset
    prep_kernel<<<NB_TOTAL, 256>>>((const float4*)video, (const float4*)audio,
                                   Wv, Wa, W1, vh, ah, bvw, baw, b1w);

    // merged projections (z=0 video, z=1 audio)
    proj_gemm<<<dim3(DMc / 128, MROWS / 128, 2), 256, GSM_TOTAL>>>(
        vh, bvw, bv, gv, ah, baw, ba, ga);

    // layernorms (warp-per-row, both tensors in one launch)
    ln8_kernel<<<dim3(MROWS / 8, 2), 256>>>();

    // sliding-window shift + context + l2norm + X build
    shiftx_kernel<<<Bc * (Tc / TCHUNK) / 8, 256>>>(theta);

    // gate MLP (fused gelu + W2 reduction) + last-CTA gate/blend
    mlp_gemm<<<dim3(HIDc / 128, MROWS / 128), 256, GSM_TOTAL>>>(
        xh, b1w, b1, W2, gpart, b2, out);
}

// round 14
// speedup vs baseline: 1.2859x; 1.2859x over previous
#include <cuda_runtime.h>
#include <cuda_fp16.h>
#include <math.h>
#include <stdint.h>

// ---------------- problem constants ----------------
#define Bc     8
#define Tc     2048
#define VDIMc  1024
#define ADIMc  768
#define DMc    256
#define HIDc   1024
#define MROWS  (Bc * Tc)          // 16384
#define XDIM   (3 * DMc)          // 768

// ---------------- scratch (device globals; no allocation allowed) ----------------
__device__ float g_v   [MROWS * DMc];
__device__ float g_a   [MROWS * DMc];
__device__ float g_actx[MROWS * DMc];
__device__ float g_part[MROWS * 8];

__device__ __half g_Vh[(size_t)MROWS * VDIMc];      // fp16 activations
__device__ __half g_Ah[(size_t)MROWS * ADIMc];
__device__ __half g_Xh[(size_t)MROWS * XDIM];
__device__ __half g_Bv[DMc  * VDIMc];               // fp16 transposed weights [N,K]
__device__ __half g_Ba[DMc  * ADIMc];
__device__ __half g_B1[HIDc * XDIM];

// ---------------- helpers ----------------
__device__ __forceinline__ uint32_t smem_u32(const void* p) {
    uint32_t a;
    asm("{ .reg .u64 t; cvta.to.shared.u64 t, %1; cvt.u32.u64 %0, t; }" : "=r"(a) : "l"(p));
    return a;
}
__device__ __forceinline__ float gelu_exact(float h) {
    return 0.5f * h * (1.f + erff(h * 0.70710678118654752f));
}

#define LDSM4(rg, addr) \
    asm volatile("ldmatrix.sync.aligned.m8n8.x4.shared.b16 {%0,%1,%2,%3}, [%4];" \
        : "=r"((rg)[0]), "=r"((rg)[1]), "=r"((rg)[2]), "=r"((rg)[3]) : "r"(addr))

#define MMA16816(d, a, b) \
    asm volatile("mma.sync.aligned.m16n8k16.row.col.f32.f16.f16.f32 " \
        "{%0,%1,%2,%3}, {%4,%5,%6,%7}, {%8,%9}, {%0,%1,%2,%3};" \
        : "+f"((d)[0]), "+f"((d)[1]), "+f"((d)[2]), "+f"((d)[3]) \
        : "r"((a)[0]), "r"((a)[1]), "r"((a)[2]), "r"((a)[3]), "r"((b)[0]), "r"((b)[1]))

#define CP_ASYNC16(dst, src) \
    asm volatile("cp.async.cg.shared.global [%0], [%1], 16;" :: "r"(dst), "l"(src) : "memory")
#define CP_COMMIT() asm volatile("cp.async.commit_group;" ::: "memory")
#define CP_WAIT1()  asm volatile("cp.async.wait_group 1;" ::: "memory")

// sub-tile: 128 rows x 64 bytes (32 fp16), XOR swizzle on 16B groups
__device__ __forceinline__ uint32_t sw_off(int r, int c16) {
    return (uint32_t)(((r << 6) + (c16 << 4)) ^ ((r & 3) << 4));
}

// ---------------- plain fp16 GEMM body: C[128,128] tile = A @ B^T (+bias) ----------------
// stage = 2 k-chunks {A0,B0,A1,B1}, 8KB sub-tiles -> 32KB/stage
#define STAGES 3
#define STAGEB 32768
static constexpr int SM_EPI    = STAGES * STAGEB;    // 98304
static constexpr int GSM_TOTAL = SM_EPI + 1536;      // 99840

template <bool FUSE>
__device__ __forceinline__ void gemm_body(
    char* smem, const __half* __restrict__ A, const __half* __restrict__ Bm,
    const float* __restrict__ bias, const float* __restrict__ W2,
    float* __restrict__ out, int K, int Ntot, int bx, int by, int nxt)
{
    const uint32_t sbase = smem_u32(smem);
    const int tid  = threadIdx.x;
    const int lane = tid & 31, warp = tid >> 5;
    const int wm = warp >> 2, wn = warp & 3;          // 2 x 4 warp grid (64m x 32n)

    float* sBias = (float*)(smem + SM_EPI);
    float* sW2   = (float*)(smem + SM_EPI + 512);
    float* sRow  = (float*)(smem + SM_EPI + 1024);
    if (tid < 128) {
        sBias[tid] = bias[bx * 128 + tid];
        if (FUSE) { sW2[tid] = W2[bx * 128 + tid]; sRow[tid] = 0.f; }
    }

    const int ni = K >> 6;            // dual-chunk iterations (64 K each)
    const int cr = tid >> 2, cc = tid & 3;

    const __half* Ab = A  + (size_t)(by * 128 + cr) * K + cc * 8;
    const __half* Bb = Bm + (size_t)(bx * 128 + cr) * K + cc * 8;

    float acc[4][4][4];
#pragma unroll
    for (int i = 0; i < 4; i++)
#pragma unroll
        for (int j = 0; j < 4; j++)
#pragma unroll
            for (int q = 0; q < 4; q++) acc[i][j][q] = 0.f;

    auto load_stage = [&](int stage, int it) {
        const uint32_t s0 = sbase + stage * STAGEB;
#pragma unroll
        for (int h = 0; h < 2; h++) {
            const int kofs = (2 * it + h) * 32;
            const __half* a0 = Ab + kofs;
            const __half* b0 = Bb + kofs;
            const uint32_t sA = s0 + h * 16384;
            const uint32_t sB = sA + 8192;
            CP_ASYNC16(sA + sw_off(cr,      cc), a0);
            CP_ASYNC16(sA + sw_off(cr + 64, cc), a0 + (size_t)64 * K);
            CP_ASYNC16(sB + sw_off(cr,      cc), b0);
            CP_ASYNC16(sB + sw_off(cr + 64, cc), b0 + (size_t)64 * K);
        }
    };

    load_stage(0, 0); CP_COMMIT();
    load_stage(1, 1); CP_COMMIT();

    const int arow  = wm * 64 + (lane & 15);
    const int acsel = lane >> 4;
    const int brow  = wn * 32 + (lane & 7) + ((lane >> 4) << 3);
    const int bcsel = (lane >> 3) & 1;

    for (int it = 0; it < ni; it++) {
        CP_WAIT1();
        __syncthreads();

        const int nx = it + 2;
        if (nx < ni) load_stage(nx % STAGES, nx);
        CP_COMMIT();

#pragma unroll
        for (int h = 0; h < 2; h++) {
            const uint32_t sA = sbase + (it % STAGES) * STAGEB + h * 16384;
            const uint32_t sB = sA + 8192;
#pragma unroll
            for (int ks = 0; ks < 2; ks++) {
                uint32_t afr[4][4], bfr[2][4];
#pragma unroll
                for (int mt = 0; mt < 4; mt++)
                    LDSM4(afr[mt], sA + sw_off(arow + mt * 16, ks * 2 + acsel));
#pragma unroll
                for (int nb = 0; nb < 2; nb++)
                    LDSM4(bfr[nb], sB + sw_off(brow + nb * 16, ks * 2 + bcsel));
#pragma unroll
                for (int mt = 0; mt < 4; mt++) {
#pragma unroll
                    for (int n8 = 0; n8 < 4; n8++) {
                        uint32_t bb[2] = { bfr[n8 >> 1][(n8 & 1) * 2], bfr[n8 >> 1][(n8 & 1) * 2 + 1] };
                        MMA16816(acc[mt][n8], afr[mt], bb);
                    }
                }
            }
        }
        // no trailing sync: next iteration's leading sync protects the stage
    }

    // ---- epilogue ----
    if (!FUSE) {
#pragma unroll
        for (int mt = 0; mt < 4; mt++) {
            const int row = by * 128 + wm * 64 + mt * 16 + (lane >> 2);
#pragma unroll
            for (int n8 = 0; n8 < 4; n8++) {
                const int lc  = wn * 32 + n8 * 8 + (lane & 3) * 2;
                const int col = bx * 128 + lc;
                float2 v0 = { acc[mt][n8][0] + sBias[lc], acc[mt][n8][1] + sBias[lc + 1] };
                float2 v1 = { acc[mt][n8][2] + sBias[lc], acc[mt][n8][3] + sBias[lc + 1] };
                *reinterpret_cast<float2*>(out + (size_t)row * Ntot + col)       = v0;
                *reinterpret_cast<float2*>(out + (size_t)(row + 8) * Ntot + col) = v1;
            }
        }
    } else {
#pragma unroll
        for (int mt = 0; mt < 4; mt++) {
            float pA = 0.f, pB = 0.f;
#pragma unroll
            for (int n8 = 0; n8 < 4; n8++) {
                const int lc = wn * 32 + n8 * 8 + (lane & 3) * 2;
                pA += gelu_exact(acc[mt][n8][0] + sBias[lc])     * sW2[lc];
                pA += gelu_exact(acc[mt][n8][1] + sBias[lc + 1]) * sW2[lc + 1];
                pB += gelu_exact(acc[mt][n8][2] + sBias[lc])     * sW2[lc];
                pB += gelu_exact(acc[mt][n8][3] + sBias[lc + 1]) * sW2[lc + 1];
            }
            pA += __shfl_xor_sync(0xffffffffu, pA, 1);
            pA += __shfl_xor_sync(0xffffffffu, pA, 2);
            pB += __shfl_xor_sync(0xffffffffu, pB, 1);
            pB += __shfl_xor_sync(0xffffffffu, pB, 2);
            if ((lane & 3) == 0) {
                atomicAdd(&sRow[wm * 64 + mt * 16 + (lane >> 2)],     pA);
                atomicAdd(&sRow[wm * 64 + mt * 16 + (lane >> 2) + 8], pB);
            }
        }
        __syncthreads();
        if (tid < 128)
            out[(size_t)(by * 128 + tid) * nxt + bx] = sRow[tid];
    }
}

// merged projection GEMM: z=0 -> video (K=VDIMc), z=1 -> audio (K=ADIMc)
__global__ void __launch_bounds__(256, 2)
proj_gemm(const __half* __restrict__ Av, const __half* __restrict__ Bv,
          const float* __restrict__ bv, float* __restrict__ ov,
          const __half* __restrict__ Aa, const __half* __restrict__ Ba,
          const float* __restrict__ ba, float* __restrict__ oa)
{
    extern __shared__ char smem[];
    if (blockIdx.z == 0)
        gemm_body<false>(smem, Av, Bv, bv, nullptr, ov, VDIMc, DMc,
                         blockIdx.x, blockIdx.y, 0);
    else
        gemm_body<false>(smem, Aa, Ba, ba, nullptr, oa, ADIMc, DMc,
                         blockIdx.x, blockIdx.y, 0);
}

// gate MLP GEMM with fused gelu + W2 partial reduction
__global__ void __launch_bounds__(256, 2)
mlp_gemm(const __half* __restrict__ A, const __half* __restrict__ Bm,
         const float* __restrict__ bias, const float* __restrict__ W2,
         float* __restrict__ out)
{
    extern __shared__ char smem[];
    gemm_body<true>(smem, A, Bm, bias, W2, out, XDIM, HIDc,
                    blockIdx.x, blockIdx.y, gridDim.x);
}

// ---------------- mega prep: activation converts + weight transposes, one launch ----------
#define NB_V (MROWS * VDIMc / 4 / 256)    // 16384
#define NB_A (MROWS * ADIMc / 4 / 256)    // 12288
#define NB_WV ((VDIMc / 32) * (DMc / 32))   // 256
#define NB_WA ((ADIMc / 32) * (DMc / 32))   // 192
#define NB_W1 ((XDIM / 32) * (HIDc / 32))   // 768
#define NB_TOTAL (NB_V + NB_A + NB_WV + NB_WA + NB_W1)

__device__ __forceinline__ void cvt_body(const float4* __restrict__ X,
                                         __half* __restrict__ dst, int i)
{
    float4 x = X[i];
    ushort4 v;
    v.x = __half_as_ushort(__float2half(x.x));
    v.y = __half_as_ushort(__float2half(x.y));
    v.z = __half_as_ushort(__float2half(x.z));
    v.w = __half_as_ushort(__float2half(x.w));
    *reinterpret_cast<ushort4*>(dst + 4 * (size_t)i) = v;
}

__device__ __forceinline__ void wcvtT_body(float (*tile)[33],
                                           const float* __restrict__ W,
                                           __half* __restrict__ dst,
                                           int K, int N, int bxk, int byn)
{
    const int k0 = bxk * 32, n0 = byn * 32;
    const int tx = threadIdx.x & 31, ty8 = threadIdx.x >> 5;
#pragma unroll
    for (int i = 0; i < 4; i++) {
        int ty = ty8 + i * 8;
        tile[ty][tx] = W[(size_t)(k0 + ty) * N + n0 + tx];
    }
    __syncthreads();
#pragma unroll
    for (int i = 0; i < 4; i++) {
        int ny = ty8 + i * 8;
        dst[(size_t)(n0 + ny) * K + k0 + tx] = __float2half(tile[tx][ny]);
    }
}

__global__ __launch_bounds__(256)
void prep_kernel(const float4* __restrict__ video, const float4* __restrict__ audio,
                 const float* __restrict__ Wv, const float* __restrict__ Wa,
                 const float* __restrict__ W1,
                 __half* __restrict__ vh, __half* __restrict__ ah,
                 __half* __restrict__ bvw, __half* __restrict__ baw,
                 __half* __restrict__ b1w)
{
    __shared__ float tile[32][33];
    const int bid = blockIdx.x;
    if (bid < NB_V) {
        cvt_body(video, vh, bid * 256 + threadIdx.x);
    } else if (bid < NB_V + NB_A) {
        cvt_body(audio, ah, (bid - NB_V) * 256 + threadIdx.x);
    } else if (bid < NB_V + NB_A + NB_WV) {
        int j = bid - (NB_V + NB_A);
        wcvtT_body(tile, Wv, bvw, VDIMc, DMc, j % (VDIMc / 32), j / (VDIMc / 32));
    } else if (bid < NB_V + NB_A + NB_WV + NB_WA) {
        int j = bid - (NB_V + NB_A + NB_WV);
        wcvtT_body(tile, Wa, baw, ADIMc, DMc, j % (ADIMc / 32), j / (ADIMc / 32));
    } else {
        int j = bid - (NB_V + NB_A + NB_WV + NB_WA);
        wcvtT_body(tile, W1, b1w, XDIM, HIDc, j % (XDIM / 32), j / (XDIM / 32));
    }
}

// ---------------- warp-per-row LayerNorm (DM=256), 8 rows/block, both tensors ----------------
__global__ __launch_bounds__(256)
void ln8_kernel()
{
    const int lane = threadIdx.x & 31, w = threadIdx.x >> 5;
    float* X = (blockIdx.y == 0) ? g_v : g_a;
    const size_t row = (size_t)blockIdx.x * 8 + w;
    float4* p = reinterpret_cast<float4*>(X + row * DMc);
    float4 x0 = p[lane], x1 = p[lane + 32];
    float s = x0.x + x0.y + x0.z + x0.w + x1.x + x1.y + x1.z + x1.w;
#pragma unroll
    for (int o = 16; o > 0; o >>= 1) s += __shfl_xor_sync(0xffffffffu, s, o);
    float mu = s * (1.f / DMc);
    x0.x -= mu; x0.y -= mu; x0.z -= mu; x0.w -= mu;
    x1.x -= mu; x1.y -= mu; x1.z -= mu; x1.w -= mu;
    float q = x0.x*x0.x + x0.y*x0.y + x0.z*x0.z + x0.w*x0.w
            + x1.x*x1.x + x1.y*x1.y + x1.z*x1.z + x1.w*x1.w;
#pragma unroll
    for (int o = 16; o > 0; o >>= 1) q += __shfl_xor_sync(0xffffffffu, q, o);
    float r = rsqrtf(q * (1.f / DMc) + 1e-5f);
    x0.x *= r; x0.y *= r; x0.z *= r; x0.w *= r;
    x1.x *= r; x1.y *= r; x1.z *= r; x1.w *= r;
    p[lane] = x0; p[lane + 32] = x1;
}

// ---------------- pair shift + window + l2norm + X build ----------------
// One warp handles rows t=2u and t+1 (shared window stream); lane owns 8 d's.
// Grid: MROWS/2 warps = 8192 -> 1024 blocks. Zero block barriers.
__global__ __launch_bounds__(256)
void shiftx_kernel(const float* __restrict__ theta)
{
    const int lane = threadIdx.x & 31, w = threadIdx.x >> 5;
    const int job = blockIdx.x * 8 + w;                  // 0..8191
    const int b = job / (Tc / 2);
    const int t = (job % (Tc / 2)) * 2;                  // even row; pair is (t, t+1)

    float th = fminf(fmaxf(theta[0], -12.f), 12.f);
    float delta = 2.f + 4.f / (1.f + expf(-th));
    float dl = fminf(fmaxf(delta, 0.f), (float)(Tc - 1));
    float nf = floorf(dl);
    float alpha = dl - nf;
    const int ni = (int)nf;

    const int lo0 = max(0, t - 5);                       // window start for row t
    const int lo1 = max(0, t - 4);                       // window start for row t+1
    const float* abase = g_a + (size_t)b * Tc * DMc;
    const int d0 = lane * 8;

    auto loadrow = [&](int r, float* dst) {
        const float4* p = reinterpret_cast<const float4*>(abase + (size_t)r * DMc + d0);
        float4 a = p[0], c = p[1];
        dst[0] = a.x; dst[1] = a.y; dst[2] = a.z; dst[3] = a.w;
        dst[4] = c.x; dst[5] = c.y; dst[6] = c.z; dst[7] = c.w;
    };

    float sum0[8], sum1[8], r0[8], r1[8];
#pragma unroll
    for (int j = 0; j < 8; j++) { sum0[j] = 0.f; sum1[j] = 0.f; }

    int jrow = max(0, lo0 - ni);
    loadrow(jrow, r0);
    loadrow(min(jrow + 1, Tc - 1), r1);

    for (int tau = lo0; tau <= t + 1; tau++) {
        const int i0 = max(0, tau - ni);
        if (i0 != jrow) {                                // advances by exactly 1
#pragma unroll
            for (int j = 0; j < 8; j++) r0[j] = r1[j];
            loadrow(min(i0 + 1, Tc - 1), r1);
            jrow = i0;
        }
        const bool in0 = (tau <= t);                     // window of row t
        const bool in1 = (tau >= lo1);                   // window of row t+1
#pragma unroll
        for (int j = 0; j < 8; j++) {
            float ash = (1.f - alpha) * r0[j] + alpha * r1[j];
            if (in0) sum0[j] += ash;
            if (in1) sum1[j] += ash;
        }
    }

    // ---- emit both rows ----
#pragma unroll
    for (int rr = 0; rr < 2; rr++) {
        const int tt = t + rr;
        const size_t row = (size_t)b * Tc + tt;
        const float inv = 1.f / (float)min(tt + 1, 6);
        float actx[8];
        float* s = rr ? sum1 : sum0;
#pragma unroll
        for (int j = 0; j < 8; j++) actx[j] = s[j] * inv;
        {
            float4* po = reinterpret_cast<float4*>(g_actx + row * DMc + d0);
            po[0] = make_float4(actx[0], actx[1], actx[2], actx[3]);
            po[1] = make_float4(actx[4], actx[5], actx[6], actx[7]);
        }
        float vv[8];
        {
            const float4* pv = reinterpret_cast<const float4*>(g_v + row * DMc + d0);
            float4 a = pv[0], c = pv[1];
            vv[0] = a.x; vv[1] = a.y; vv[2] = a.z; vv[3] = a.w;
            vv[4] = c.x; vv[5] = c.y; vv[6] = c.z; vv[7] = c.w;
        }
        float ssv = 0.f, ssa = 0.f;
#pragma unroll
        for (int j = 0; j < 8; j++) { ssv += vv[j] * vv[j]; ssa += actx[j] * actx[j]; }
#pragma unroll
        for (int o = 16; o > 0; o >>= 1) {
            ssv += __shfl_xor_sync(0xffffffffu, ssv, o);
            ssa += __shfl_xor_sync(0xffffffffu, ssa, o);
        }
        const float rv = 1.f / fmaxf(sqrtf(ssv), 1e-8f);
        const float ra = 1.f / fmaxf(sqrtf(ssa), 1e-8f);

        __half h8[8];
        const size_t base = row * XDIM;
#pragma unroll
        for (int j = 0; j < 8; j++) h8[j] = __float2half(actx[j] * ra);
        *reinterpret_cast<uint4*>(g_Xh + base + d0) = *reinterpret_cast<uint4*>(h8);
#pragma unroll
        for (int j = 0; j < 8; j++) h8[j] = __float2half(vv[j] * rv);
        *reinterpret_cast<uint4*>(g_Xh + base + DMc + d0) = *reinterpret_cast<uint4*>(h8);
#pragma unroll
        for (int j = 0; j < 8; j++) h8[j] = __float2half((actx[j] * ra) * (vv[j] * rv));
        *reinterpret_cast<uint4*>(g_Xh + base + 2 * DMc + d0) = *reinterpret_cast<uint4*>(h8);
    }
}

// ---------------- finalize: warp per row, 8 rows/block ----------------
__global__ __launch_bounds__(256)
void final_kernel(const float* __restrict__ b2, float* __restrict__ out)
{
    const int lane = threadIdx.x & 31, w = threadIdx.x >> 5;
    const size_t row = (size_t)blockIdx.x * 8 + w;
    float l = b2[0];
#pragma unroll
    for (int p = 0; p < 8; p++) l += g_part[row * 8 + p];
    l = fminf(fmaxf(l, -12.f), 12.f);
    float g = 1.f / (1.f + expf(-l));
    g = fminf(fmaxf(g, 0.05f), 0.95f);
    const float4* pa = reinterpret_cast<const float4*>(g_actx + row * DMc);
    const float4* pv = reinterpret_cast<const float4*>(g_v    + row * DMc);
    float4* po = reinterpret_cast<float4*>(out + row * DMc);
#pragma unroll
    for (int h = 0; h < 2; h++) {
        float4 a4 = pa[lane + h * 32], v4 = pv[lane + h * 32], o4;
        o4.x = g * a4.x + (1.f - g) * v4.x;
        o4.y = g * a4.y + (1.f - g) * v4.y;
        o4.z = g * a4.z + (1.f - g) * v4.z;
        o4.w = g * a4.w + (1.f - g) * v4.w;
        po[lane + h * 32] = o4;
    }
}

// ---------------- launch ----------------
extern "C" void kernel_launch(void* const* d_in, const int* in_sizes, int n_in,
                              void* d_out, int out_size)
{
    const float* video = (const float*)d_in[0];
    const float* audio = (const float*)d_in[1];
    const float* Wv    = (const float*)d_in[2];
    const float* bv    = (const float*)d_in[3];
    const float* Wa    = (const float*)d_in[4];
    const float* ba    = (const float*)d_in[5];
    const float* theta = (const float*)d_in[6];
    const float* W1    = (const float*)d_in[7];
    const float* b1    = (const float*)d_in[8];
    const float* W2    = (const float*)d_in[9];
    const float* b2    = (const float*)d_in[10];
    float* out = (float*)d_out;

    float *gv, *ga, *gpart;
    __half *vh, *ah, *xh, *bvw, *baw, *b1w;
    cudaGetSymbolAddress((void**)&gv, g_v);
    cudaGetSymbolAddress((void**)&ga, g_a);
    cudaGetSymbolAddress((void**)&gpart, g_part);
    cudaGetSymbolAddress((void**)&vh, g_Vh);
    cudaGetSymbolAddress((void**)&ah, g_Ah);
    cudaGetSymbolAddress((void**)&xh, g_Xh);
    cudaGetSymbolAddress((void**)&bvw, g_Bv);
    cudaGetSymbolAddress((void**)&baw, g_Ba);
    cudaGetSymbolAddress((void**)&b1w, g_B1);

    cudaFuncSetAttribute(proj_gemm, cudaFuncAttributeMaxDynamicSharedMemorySize, GSM_TOTAL);
    cudaFuncSetAttribute(mlp_gemm,  cudaFuncAttributeMaxDynamicSharedMemorySize, GSM_TOTAL);

    // single prep launch: both activation converts + all 3 weight transposes
    prep_kernel<<<NB_TOTAL, 256>>>((const float4*)video, (const float4*)audio,
                                   Wv, Wa, W1, vh, ah, bvw, baw, b1w);

    // merged projections (z=0 video, z=1 audio)
    proj_gemm<<<dim3(DMc / 128, MROWS / 128, 2), 256, GSM_TOTAL>>>(
        vh, bvw, bv, gv, ah, baw, ba, ga);

    // layernorms (warp-per-row, both tensors in one launch)
    ln8_kernel<<<dim3(MROWS / 8, 2), 256>>>();

    // pair shift + context + l2norm + X build (2 rows per warp)
    shiftx_kernel<<<MROWS / 16, 256>>>(theta);

    // gate MLP with fused gelu + W2 reduction
    mlp_gemm<<<dim3(HIDc / 128, MROWS / 128), 256, GSM_TOTAL>>>(
        xh, b1w, b1, W2, gpart);

    final_kernel<<<MROWS / 8, 256>>>(b2, out);
}